// round 3
// baseline (speedup 1.0000x reference)
#include <cuda_runtime.h>
#include <cuda_bf16.h>
#include <cstdint>

#define N_WORDS 30000
#define EMB_DIM 784
#define MAT_DIM 28
#define BATCH   1024
#define SEQ     64

// 4 warps per block, one block per sequence. Each warp owns a 16-token chunk.
#define WARPS_PER_BLOCK 4
#define CHUNK 16
#define THREADS (WARPS_PER_BLOCK * 32)

// ---------------------------------------------------------------------------
// f32x2 packed-FMA helpers (FFMA2 is only reachable via PTX fma.rn.f32x2)
// ---------------------------------------------------------------------------
__device__ __forceinline__ unsigned long long pack2(float x, float y) {
    unsigned long long r;
    asm("mov.b64 %0, {%1, %2};" : "=l"(r) : "f"(x), "f"(y));
    return r;
}
__device__ __forceinline__ void unpack2(unsigned long long d, float& x, float& y) {
    asm("mov.b64 {%0, %1}, %2;" : "=f"(x), "=f"(y) : "l"(d));
}
__device__ __forceinline__ void fma2(unsigned long long& d,
                                     unsigned long long a,
                                     unsigned long long b) {
    asm("fma.rn.f32x2 %0, %1, %2, %0;" : "+l"(d) : "l"(a), "l"(b));
}

// cp.async 16B global -> shared (L2-cached path; table reuse lives in L2)
__device__ __forceinline__ void cp16(void* s, const void* g) {
    unsigned saddr = (unsigned)__cvta_generic_to_shared(s);
    asm volatile("cp.async.cg.shared.global [%0], [%1], 16;\n"
                 :: "r"(saddr), "l"(g) : "memory");
}
__device__ __forceinline__ void cp_commit() {
    asm volatile("cp.async.commit_group;\n" ::: "memory");
}
__device__ __forceinline__ void cp_wait0() {
    asm volatile("cp.async.wait_group 0;\n" ::: "memory");
}

// ---------------------------------------------------------------------------
// cur(row r, in registers of lane r) = cur @ M, with M (28x28 row-major) in
// shared memory. All lanes read the same M addresses -> LDS broadcast (free
// on the crossbar). 392 f32x2 FMAs + 196 LDS.128 per call.
// ---------------------------------------------------------------------------
__device__ __forceinline__ void matmul28(float cur[MAT_DIM], const float* sM) {
    unsigned long long acc[14];
#pragma unroll
    for (int j = 0; j < 14; ++j) acc[j] = 0ull;

#pragma unroll
    for (int k = 0; k < MAT_DIM; ++k) {
        unsigned long long a2 = pack2(cur[k], cur[k]);
        const ulonglong2* row = reinterpret_cast<const ulonglong2*>(sM + k * MAT_DIM);
#pragma unroll
        for (int j = 0; j < 7; ++j) {
            ulonglong2 b = row[j];                 // LDS.128 broadcast: M[k][4j..4j+3]
            fma2(acc[2 * j],     a2, b.x);
            fma2(acc[2 * j + 1], a2, b.y);
        }
    }
#pragma unroll
    for (int j = 0; j < 14; ++j) unpack2(acc[j], cur[2 * j], cur[2 * j + 1]);
}

__device__ __forceinline__ void store_row_shared(float* dst, const float cur[MAT_DIM]) {
    float4* o = reinterpret_cast<float4*>(dst);
#pragma unroll
    for (int j = 0; j < 7; ++j)
        o[j] = make_float4(cur[4 * j], cur[4 * j + 1], cur[4 * j + 2], cur[4 * j + 3]);
}

__global__ void __launch_bounds__(THREADS)
w2m_kernel(const int* __restrict__ sent,
           const float* __restrict__ table,
           float* __restrict__ out) {
    __shared__ __align__(16) float mbuf[WARPS_PER_BLOCK][2][EMB_DIM]; // double-buffered M
    __shared__ __align__(16) float comb[WARPS_PER_BLOCK][EMB_DIM];    // chunk partials

    const int seq  = blockIdx.x;
    const int w    = threadIdx.x >> 5;
    const int lane = threadIdx.x & 31;
    const bool active = (lane < MAT_DIM);
    const int r = lane;   // row owned by this lane

    // Each lane<16 holds one token index of this warp's chunk.
    int sidx = 0;
    if (lane < CHUNK) sidx = sent[(size_t)seq * SEQ + w * CHUNK + lane];

    float cur[MAT_DIM];

    // Prefetch token 0 of the chunk.
    {
        int idx0 = __shfl_sync(0xffffffffu, sidx, 0);
        const float* src = table + (size_t)idx0 * EMB_DIM;
        float* dst = mbuf[w][0];
        for (int i = lane; i < EMB_DIM / 4; i += 32) cp16(dst + i * 4, src + i * 4);
        cp_commit();
    }

#pragma unroll 1
    for (int t = 0; t < CHUNK; ++t) {
        cp_wait0();
        __syncwarp();
        // Prefetch next token into the other buffer; in flight during compute(t).
        if (t < CHUNK - 1) {
            int idx = __shfl_sync(0xffffffffu, sidx, t + 1);
            const float* src = table + (size_t)idx * EMB_DIM;
            float* dst = mbuf[w][(t + 1) & 1];
            for (int i = lane; i < EMB_DIM / 4; i += 32) cp16(dst + i * 4, src + i * 4);
            cp_commit();
        }
        if (active) {
            if (t == 0) {
                const float4* rowp =
                    reinterpret_cast<const float4*>(&mbuf[w][0][r * MAT_DIM]);
#pragma unroll
                for (int j = 0; j < 7; ++j) {
                    float4 v = rowp[j];
                    cur[4 * j] = v.x; cur[4 * j + 1] = v.y;
                    cur[4 * j + 2] = v.z; cur[4 * j + 3] = v.w;
                }
            } else {
                matmul28(cur, mbuf[w][t & 1]);
            }
        }
    }

    // Publish chunk partial P_w.
    if (active) store_row_shared(&comb[w][r * MAT_DIM], cur);
    __syncthreads();

    // Tree combine (associative, order-preserving):
    // step A: warp0: P0@P1 ; warp2: P2@P3
    if (active && (w == 0 || w == 2)) matmul28(cur, comb[w + 1]);
    if (active && w == 2) store_row_shared(&comb[2][r * MAT_DIM], cur);
    __syncthreads();

    // step B: warp0: (P0@P1) @ (P2@P3) -> final, store to gmem.
    if (active && w == 0) {
        matmul28(cur, comb[2]);
        float4* o = reinterpret_cast<float4*>(out + (size_t)seq * EMB_DIM + r * MAT_DIM);
#pragma unroll
        for (int j = 0; j < 7; ++j)
            o[j] = make_float4(cur[4 * j], cur[4 * j + 1], cur[4 * j + 2], cur[4 * j + 3]);
    }
}

extern "C" void kernel_launch(void* const* d_in, const int* in_sizes, int n_in,
                              void* d_out, int out_size) {
    // Identify inputs by element count (sent: 1024*64, table: 30001*784).
    const int* sent;
    const float* table;
    if (in_sizes[0] == BATCH * SEQ) {
        sent  = (const int*)d_in[0];
        table = (const float*)d_in[1];
    } else {
        sent  = (const int*)d_in[1];
        table = (const float*)d_in[0];
    }
    float* out = (float*)d_out;
    (void)n_in; (void)out_size;

    w2m_kernel<<<BATCH, THREADS>>>(sent, table, out);
}